// round 4
// baseline (speedup 1.0000x reference)
#include <cuda_runtime.h>
#include <cuda_bf16.h>

// MGIoU2D+ loss, 2 boxes per thread.
// - exact angular comparator sort (no atan2)
// - convexity penalty computed up-front, originals die after sorting
// - other-poly projections use sorted arrays (min/max permutation-invariant)
// - s1/hull interval algebra, single divide per axis, folded constants

__device__ __forceinline__ bool ang_less(float ux, float uy, float vx, float vy) {
    bool lu = uy < 0.0f;
    bool lv = vy < 0.0f;
    if (lu != lv) return lu;
    return (ux * vy - uy * vx) > 0.0f;
}

__device__ __forceinline__ void sort_angular(float u[4], float v[4]) {
#define CMPSWAP(i, j)                                                        \
    {                                                                        \
        bool sw = ang_less(u[j], v[j], u[i], v[i]);                          \
        float sx = sw ? u[j] : u[i];                                         \
        float sy = sw ? v[j] : v[i];                                         \
        float bx = sw ? u[i] : u[j];                                         \
        float by = sw ? v[i] : v[j];                                         \
        u[i] = sx; v[i] = sy; u[j] = bx; v[j] = by;                          \
    }
    CMPSWAP(0, 1) CMPSWAP(2, 3) CMPSWAP(0, 2) CMPSWAP(1, 3) CMPSWAP(1, 2)
#undef CMPSWAP
}

// center around mean, sort angularly, restore to absolute coords
__device__ __forceinline__ void sort_poly(float x[4], float y[4]) {
    float cx = (x[0] + x[1] + x[2] + x[3]) * 0.25f;
    float cy = (y[0] + y[1] + y[2] + y[3]) * 0.25f;
#pragma unroll
    for (int i = 0; i < 4; i++) { x[i] -= cx; y[i] -= cy; }
    sort_angular(x, y);
#pragma unroll
    for (int i = 0; i < 4; i++) { x[i] += cx; y[i] += cy; }
}

// S-terms (inter/uni + uni/hull) for the 4 axes owned by sorted poly S,
// projecting sorted other-poly O. Both arrays sorted -> 3-dot trick on S.
__device__ __forceinline__ float giou_axes(const float sx[4], const float sy[4],
                                           const float ox[4], const float oy[4]) {
    float g = 0.0f;
#pragma unroll
    for (int k = 0; k < 4; k++) {
        int k1 = (k + 1) & 3, k2 = (k + 2) & 3, k3 = (k + 3) & 3;
        float nx = sy[k1] - sy[k];
        float ny = sx[k] - sx[k1];   // normal = (e.y, -e.x)

        // own poly: edge-k endpoints project equally -> 3 dots
        float a = fmaf(sx[k], nx, sy[k] * ny);
        float b = fmaf(sx[k2], nx, sy[k2] * ny);
        float c = fmaf(sx[k3], nx, sy[k3] * ny);
        float mn1 = fminf(a, fminf(b, c));
        float mx1 = fmaxf(a, fmaxf(b, c));

        float e0 = fmaf(ox[0], nx, oy[0] * ny);
        float e1 = fmaf(ox[1], nx, oy[1] * ny);
        float e2 = fmaf(ox[2], nx, oy[2] * ny);
        float e3 = fmaf(ox[3], nx, oy[3] * ny);
        float mn2 = fminf(fminf(e0, e1), fminf(e2, e3));
        float mx2 = fmaxf(fmaxf(e0, e1), fmaxf(e2, e3));

        float s1   = fminf(mx1, mx2) - fmaxf(mn1, mn2);
        float hull = fmaxf(mx1, mx2) - fminf(mn1, mn2);
        float inter = fmaxf(s1, 0.0f);
        float uni   = hull + fminf(s1, 0.0f);   // len1+len2-inter == s1+hull-inter
        // inter/uni + uni/hull == (inter*hull + uni*uni) / (uni*hull)
        float num = fmaf(inter, hull, uni * uni);
        g += __fdividef(num, uni * hull);
    }
    return g;
}

// convexity penalty sum (original vertex order), before sorting destroys px/py
__device__ __forceinline__ float convex_pen(const float px[4], const float py[4]) {
    float cr[4];
#pragma unroll
    for (int i = 0; i < 4; i++) {
        int ip = (i + 3) & 3, in = (i + 1) & 3;
        float e1x = px[ip] - px[i], e1y = py[ip] - py[i];
        float e2x = px[in] - px[i], e2y = py[in] - py[i];
        cr[i] = e1x * e2y - e1y * e2x;
    }
    float sref = (cr[0] < 0.0f) ? -1.0f : 1.0f;   // sign(c0), zero -> +1
    return fmaxf(-sref * cr[0], 0.0f) + fmaxf(-sref * cr[1], 0.0f) +
           fmaxf(-sref * cr[2], 0.0f) + fmaxf(-sref * cr[3], 0.0f);
}

__device__ __forceinline__ float box_loss(float px[4], float py[4],
                                          float tx[4], float ty[4]) {
    float pen = convex_pen(px, py);     // originals consumed here
    sort_poly(px, py);                  // arrays become sorted in place
    sort_poly(tx, ty);

    float S = giou_axes(px, py, tx, ty)   // 4 pred axes
            + giou_axes(tx, ty, px, py);  // 4 target axes

    // loss = (1 - (S-8)/8)*0.5 + 0.1*pen/4 = 1 - S/16 + 0.025*pen
    return fmaf(S, -0.0625f, fmaf(pen, 0.025f, 1.0f));
}

__global__ __launch_bounds__(128)
void mgiou2dplus_kernel(const float4* __restrict__ pred4,
                        const float4* __restrict__ targ4,
                        float* __restrict__ out, int B) {
    int t = blockIdx.x * blockDim.x + threadIdx.x;
    int b0 = 2 * t;
    if (b0 >= B) return;
    int b1 = (b0 + 1 < B) ? (b0 + 1) : b0;

    float4 pA0 = pred4[2 * b0], pA1 = pred4[2 * b0 + 1];
    float4 tA0 = targ4[2 * b0], tA1 = targ4[2 * b0 + 1];
    float4 pB0 = pred4[2 * b1], pB1 = pred4[2 * b1 + 1];
    float4 tB0 = targ4[2 * b1], tB1 = targ4[2 * b1 + 1];

    float pxA[4] = {pA0.x, pA0.z, pA1.x, pA1.z};
    float pyA[4] = {pA0.y, pA0.w, pA1.y, pA1.w};
    float txA[4] = {tA0.x, tA0.z, tA1.x, tA1.z};
    float tyA[4] = {tA0.y, tA0.w, tA1.y, tA1.w};

    float pxB[4] = {pB0.x, pB0.z, pB1.x, pB1.z};
    float pyB[4] = {pB0.y, pB0.w, pB1.y, pB1.w};
    float txB[4] = {tB0.x, tB0.z, tB1.x, tB1.z};
    float tyB[4] = {tB0.y, tB0.w, tB1.y, tB1.w};

    float lossA = box_loss(pxA, pyA, txA, tyA);
    float lossB = box_loss(pxB, pyB, txB, tyB);

    out[b0] = lossA;
    if (b0 + 1 < B) out[b0 + 1] = lossB;
}

extern "C" void kernel_launch(void* const* d_in, const int* in_sizes, int n_in,
                              void* d_out, int out_size) {
    const float4* pred = (const float4*)d_in[0];
    const float4* targ = (const float4*)d_in[1];
    float* out = (float*)d_out;
    int B = in_sizes[0] / 8;                  // [B,4,2] f32
    int nthreads = (B + 1) / 2;
    int threads = 128;
    int blocks = (nthreads + threads - 1) / threads;
    mgiou2dplus_kernel<<<blocks, threads>>>(pred, targ, out, B);
}

// round 5
// speedup vs baseline: 1.0992x; 1.0992x over previous
#include <cuda_runtime.h>
#include <cuda_bf16.h>
#include <cstdint>

// MGIoU2D+ loss, 2 boxes per thread, f32x2-packed dot products (lane0=boxA, lane1=boxB).
// Sorts / min-max / GIoU tail stay scalar (no packed FMNMX on sm_103a).

using u64 = unsigned long long;

__device__ __forceinline__ u64 pk2(float a, float b) {
    u64 r; asm("mov.b64 %0, {%1, %2};" : "=l"(r) : "f"(a), "f"(b)); return r;
}
__device__ __forceinline__ void unpk2(u64 v, float& a, float& b) {
    asm("mov.b64 {%0, %1}, %2;" : "=f"(a), "=f"(b) : "l"(v));
}
__device__ __forceinline__ u64 mul2(u64 a, u64 b) {
    u64 r; asm("mul.rn.f32x2 %0, %1, %2;" : "=l"(r) : "l"(a), "l"(b)); return r;
}
__device__ __forceinline__ u64 add2(u64 a, u64 b) {
    u64 r; asm("add.rn.f32x2 %0, %1, %2;" : "=l"(r) : "l"(a), "l"(b)); return r;
}
__device__ __forceinline__ u64 fma2(u64 a, u64 b, u64 c) {
    u64 r; asm("fma.rn.f32x2 %0, %1, %2, %3;" : "=l"(r) : "l"(a), "l"(b), "l"(c)); return r;
}
// a - b  (exact: fma(b, -1, a))
#define NEG1_2 0xBF800000BF800000ULL
__device__ __forceinline__ u64 sub2(u64 a, u64 b) { return fma2(b, NEG1_2, a); }

__device__ __forceinline__ bool ang_less(float ux, float uy, float vx, float vy) {
    bool lu = uy < 0.0f;
    bool lv = vy < 0.0f;
    if (lu != lv) return lu;
    return (ux * vy - uy * vx) > 0.0f;
}

// center at mean, angular sort in place (leaves coords centered), outputs center
__device__ __forceinline__ void sort_poly_centered(float x[4], float y[4],
                                                   float& cx, float& cy) {
    cx = ((x[0] + x[1]) + (x[2] + x[3])) * 0.25f;
    cy = ((y[0] + y[1]) + (y[2] + y[3])) * 0.25f;
#pragma unroll
    for (int i = 0; i < 4; i++) { x[i] -= cx; y[i] -= cy; }
#define CMPSWAP(i, j)                                                        \
    {                                                                        \
        bool sw = ang_less(x[j], y[j], x[i], y[i]);                          \
        float sx = sw ? x[j] : x[i];                                         \
        float sy = sw ? y[j] : y[i];                                         \
        float bx = sw ? x[i] : x[j];                                         \
        float by = sw ? y[i] : y[j];                                         \
        x[i] = sx; y[i] = sy; x[j] = bx; y[j] = by;                          \
    }
    CMPSWAP(0, 1) CMPSWAP(2, 3) CMPSWAP(0, 2) CMPSWAP(1, 3) CMPSWAP(1, 2)
#undef CMPSWAP
}

// scalar GIoU-1d S-term: inter/uni + uni/hull
__device__ __forceinline__ float giou_term(float a, float b, float c,
                                           float e0, float e1, float e2, float e3) {
    float mn1 = fminf(a, fminf(b, c));
    float mx1 = fmaxf(a, fmaxf(b, c));
    float mn2 = fminf(fminf(e0, e1), fminf(e2, e3));
    float mx2 = fmaxf(fmaxf(e0, e1), fmaxf(e2, e3));
    float s1   = fminf(mx1, mx2) - fmaxf(mn1, mn2);
    float hull = fmaxf(mx1, mx2) - fminf(mn1, mn2);
    float inter = fmaxf(s1, 0.0f);
    float uni   = hull + fminf(s1, 0.0f);
    float num = fmaf(inter, hull, uni * uni);
    return __fdividef(num, uni * hull);
}

// 4 axes owned by packed-sorted poly S, projecting packed-sorted poly O.
// Own-poly uses the shared-endpoint identity (3 dots). Accumulates into SA/SB.
__device__ __forceinline__ void axes4(const u64 sx[4], const u64 sy[4],
                                      const u64 ox[4], const u64 oy[4],
                                      float& SA, float& SB) {
#pragma unroll
    for (int k = 0; k < 4; k++) {
        int k1 = (k + 1) & 3, k2 = (k + 2) & 3, k3 = (k + 3) & 3;
        u64 nx = sub2(sy[k1], sy[k]);   // e.y
        u64 ny = sub2(sx[k], sx[k1]);   // -e.x
        u64 a = fma2(sx[k],  nx, mul2(sy[k],  ny));
        u64 b = fma2(sx[k2], nx, mul2(sy[k2], ny));
        u64 c = fma2(sx[k3], nx, mul2(sy[k3], ny));
        u64 f0 = fma2(ox[0], nx, mul2(oy[0], ny));
        u64 f1 = fma2(ox[1], nx, mul2(oy[1], ny));
        u64 f2 = fma2(ox[2], nx, mul2(oy[2], ny));
        u64 f3 = fma2(ox[3], nx, mul2(oy[3], ny));
        float aA, aB, bA, bB, cA, cB, e0A, e0B, e1A, e1B, e2A, e2B, e3A, e3B;
        unpk2(a, aA, aB);   unpk2(b, bA, bB);   unpk2(c, cA, cB);
        unpk2(f0, e0A, e0B); unpk2(f1, e1A, e1B);
        unpk2(f2, e2A, e2B); unpk2(f3, e3A, e3B);
        SA += giou_term(aA, bA, cA, e0A, e1A, e2A, e3A);
        SB += giou_term(aB, bB, cB, e0B, e1B, e2B, e3B);
    }
}

// convexity penalty sum, original vertex order (scalar, per box)
__device__ __forceinline__ float convex_pen(const float px[4], const float py[4]) {
    float cr[4];
#pragma unroll
    for (int i = 0; i < 4; i++) {
        int ip = (i + 3) & 3, in = (i + 1) & 3;
        float e1x = px[ip] - px[i], e1y = py[ip] - py[i];
        float e2x = px[in] - px[i], e2y = py[in] - py[i];
        cr[i] = e1x * e2y - e1y * e2x;
    }
    float sref = (cr[0] < 0.0f) ? -1.0f : 1.0f;   // sign(c0), zero -> +1
    return fmaxf(-sref * cr[0], 0.0f) + fmaxf(-sref * cr[1], 0.0f) +
           fmaxf(-sref * cr[2], 0.0f) + fmaxf(-sref * cr[3], 0.0f);
}

__global__ __launch_bounds__(128)
void mgiou2dplus_kernel(const float4* __restrict__ pred4,
                        const float4* __restrict__ targ4,
                        float* __restrict__ out, int B) {
    int t = blockIdx.x * blockDim.x + threadIdx.x;
    int b0 = 2 * t;
    if (b0 >= B) return;
    int b1 = (b0 + 1 < B) ? (b0 + 1) : b0;

    float4 pA0 = pred4[2 * b0], pA1 = pred4[2 * b0 + 1];
    float4 tA0 = targ4[2 * b0], tA1 = targ4[2 * b0 + 1];
    float4 pB0 = pred4[2 * b1], pB1 = pred4[2 * b1 + 1];
    float4 tB0 = targ4[2 * b1], tB1 = targ4[2 * b1 + 1];

    float pxA[4] = {pA0.x, pA0.z, pA1.x, pA1.z};
    float pyA[4] = {pA0.y, pA0.w, pA1.y, pA1.w};
    float txA[4] = {tA0.x, tA0.z, tA1.x, tA1.z};
    float tyA[4] = {tA0.y, tA0.w, tA1.y, tA1.w};
    float pxB[4] = {pB0.x, pB0.z, pB1.x, pB1.z};
    float pyB[4] = {pB0.y, pB0.w, pB1.y, pB1.w};
    float txB[4] = {tB0.x, tB0.z, tB1.x, tB1.z};
    float tyB[4] = {tB0.y, tB0.w, tB1.y, tB1.w};

    float penA = convex_pen(pxA, pyA);
    float penB = convex_pen(pxB, pyB);

    float cpxA, cpyA, ctxA, ctyA, cpxB, cpyB, ctxB, ctyB;
    sort_poly_centered(pxA, pyA, cpxA, cpyA);
    sort_poly_centered(txA, tyA, ctxA, ctyA);
    sort_poly_centered(pxB, pyB, cpxB, cpyB);
    sort_poly_centered(txB, tyB, ctxB, ctyB);

    // pack sorted (centered) coords, restore centers with packed adds
    u64 Cpx = pk2(cpxA, cpxB), Cpy = pk2(cpyA, cpyB);
    u64 Ctx = pk2(ctxA, ctxB), Cty = pk2(ctyA, ctyB);
    u64 Px[4], Py[4], Tx[4], Ty[4];
#pragma unroll
    for (int i = 0; i < 4; i++) {
        Px[i] = add2(pk2(pxA[i], pxB[i]), Cpx);
        Py[i] = add2(pk2(pyA[i], pyB[i]), Cpy);
        Tx[i] = add2(pk2(txA[i], txB[i]), Ctx);
        Ty[i] = add2(pk2(tyA[i], tyB[i]), Cty);
    }

    float SA = 0.0f, SB = 0.0f;
    axes4(Px, Py, Tx, Ty, SA, SB);   // pred-owned axes
    axes4(Tx, Ty, Px, Py, SA, SB);   // target-owned axes

    // loss = 1 - S/16 + 0.025*pen
    float lossA = fmaf(SA, -0.0625f, fmaf(penA, 0.025f, 1.0f));
    float lossB = fmaf(SB, -0.0625f, fmaf(penB, 0.025f, 1.0f));

    out[b0] = lossA;
    if (b0 + 1 < B) out[b0 + 1] = lossB;
}

extern "C" void kernel_launch(void* const* d_in, const int* in_sizes, int n_in,
                              void* d_out, int out_size) {
    const float4* pred = (const float4*)d_in[0];
    const float4* targ = (const float4*)d_in[1];
    float* out = (float*)d_out;
    int B = in_sizes[0] / 8;                  // [B,4,2] f32
    int nthreads = (B + 1) / 2;
    int threads = 128;
    int blocks = (nthreads + threads - 1) / threads;
    mgiou2dplus_kernel<<<blocks, threads>>>(pred, targ, out, B);
}